// round 1
// baseline (speedup 1.0000x reference)
#include <cuda_runtime.h>
#include <math.h>

#define NB 32
#define C  512
#define S  3136   // 56*56
#define S4 (S/4)

// Scratch (device globals -- no allocations allowed)
__device__ float g_exp[(size_t)NB * C * S];   // unnormalized exp(7*(x - rowmax))
__device__ float g_invZ[NB * C];              // 1/rowsum
__device__ float g_B[(size_t)NB * C * C];     // bilinear (raw, then softmaxed in place)
__device__ float g_w[NB * C];                 // column sums of softmax(B)

// ---------------- block reductions ----------------
__device__ __forceinline__ float blockReduceMax(float v) {
    __shared__ float sh[32];
    int lane = threadIdx.x & 31, w = threadIdx.x >> 5;
    __syncthreads();
    #pragma unroll
    for (int o = 16; o; o >>= 1) v = fmaxf(v, __shfl_xor_sync(0xffffffffu, v, o));
    if (lane == 0) sh[w] = v;
    __syncthreads();
    int nw = (blockDim.x + 31) >> 5;
    if (w == 0) {
        v = (lane < nw) ? sh[lane] : -INFINITY;
        #pragma unroll
        for (int o = 16; o; o >>= 1) v = fmaxf(v, __shfl_xor_sync(0xffffffffu, v, o));
        if (lane == 0) sh[0] = v;
    }
    __syncthreads();
    return sh[0];
}

__device__ __forceinline__ float blockReduceSum(float v) {
    __shared__ float sh[32];
    int lane = threadIdx.x & 31, w = threadIdx.x >> 5;
    __syncthreads();
    #pragma unroll
    for (int o = 16; o; o >>= 1) v += __shfl_xor_sync(0xffffffffu, v, o);
    if (lane == 0) sh[w] = v;
    __syncthreads();
    int nw = (blockDim.x + 31) >> 5;
    if (w == 0) {
        v = (lane < nw) ? sh[lane] : 0.0f;
        #pragma unroll
        for (int o = 16; o; o >>= 1) v += __shfl_xor_sync(0xffffffffu, v, o);
        if (lane == 0) sh[0] = v;
    }
    __syncthreads();
    return sh[0];
}

// ---------------- kernel 1: per-(n,c) row: exp(7*(x-max)), 1/sum ----------------
__global__ void k_rowexp(const float* __restrict__ x) {
    size_t row = blockIdx.x;  // n*C + c
    const float4* xr = (const float4*)(x + row * S);
    float4* er = (float4*)(g_exp + row * S);

    float m = -INFINITY;
    for (int i = threadIdx.x; i < S4; i += blockDim.x) {
        float4 v = xr[i];
        m = fmaxf(m, fmaxf(fmaxf(v.x, v.y), fmaxf(v.z, v.w)));
    }
    m = blockReduceMax(m);

    float s = 0.0f;
    for (int i = threadIdx.x; i < S4; i += blockDim.x) {
        float4 v = xr[i];
        float4 e;
        e.x = __expf(7.0f * (v.x - m));
        e.y = __expf(7.0f * (v.y - m));
        e.z = __expf(7.0f * (v.z - m));
        e.w = __expf(7.0f * (v.w - m));
        s += (e.x + e.y) + (e.z + e.w);
        er[i] = e;
    }
    s = blockReduceSum(s);
    if (threadIdx.x == 0) g_invZ[row] = 1.0f / s;
}

// ---------------- kernel 2: batched SGEMM  B[n] = E[n] * X[n]^T  (512x512x3136) ----------------
// 128x128 tile, BK=8, 256 threads, 8x8 per thread.
__global__ __launch_bounds__(256, 2) void k_gemm(const float* __restrict__ x) {
    const int n = blockIdx.z;
    const float* A  = g_exp + (size_t)n * C * S;  // M x K (K-major)
    const float* Bg = x     + (size_t)n * C * S;  // N x K (K-major)
    float* Cc = g_B + (size_t)n * C * C;

    __shared__ float As[8][128];
    __shared__ float Bs[8][128];

    const int tid  = threadIdx.x;
    const int tx   = tid & 15;        // 0..15 -> N
    const int ty   = tid >> 4;        // 0..15 -> M
    const int lrow = tid >> 1;        // 0..127
    const int lcol = (tid & 1) * 4;   // 0 or 4

    const float* Aptr = A  + (size_t)(blockIdx.y * 128 + lrow) * S + lcol;
    const float* Bptr = Bg + (size_t)(blockIdx.x * 128 + lrow) * S + lcol;

    float acc[8][8];
    #pragma unroll
    for (int i = 0; i < 8; i++)
        #pragma unroll
        for (int j = 0; j < 8; j++) acc[i][j] = 0.0f;

    for (int k0 = 0; k0 < S; k0 += 8) {
        float4 av = *(const float4*)(Aptr + k0);
        float4 bv = *(const float4*)(Bptr + k0);
        __syncthreads();
        As[lcol + 0][lrow] = av.x; As[lcol + 1][lrow] = av.y;
        As[lcol + 2][lrow] = av.z; As[lcol + 3][lrow] = av.w;
        Bs[lcol + 0][lrow] = bv.x; Bs[lcol + 1][lrow] = bv.y;
        Bs[lcol + 2][lrow] = bv.z; Bs[lcol + 3][lrow] = bv.w;
        __syncthreads();
        #pragma unroll
        for (int k = 0; k < 8; k++) {
            float ar[8], br[8];
            float4 a0 = *(const float4*)(&As[k][ty * 8]);
            float4 a1 = *(const float4*)(&As[k][ty * 8 + 4]);
            float4 b0 = *(const float4*)(&Bs[k][tx * 8]);
            float4 b1 = *(const float4*)(&Bs[k][tx * 8 + 4]);
            ar[0]=a0.x; ar[1]=a0.y; ar[2]=a0.z; ar[3]=a0.w;
            ar[4]=a1.x; ar[5]=a1.y; ar[6]=a1.z; ar[7]=a1.w;
            br[0]=b0.x; br[1]=b0.y; br[2]=b0.z; br[3]=b0.w;
            br[4]=b1.x; br[5]=b1.y; br[6]=b1.z; br[7]=b1.w;
            #pragma unroll
            for (int i = 0; i < 8; i++)
                #pragma unroll
                for (int j = 0; j < 8; j++)
                    acc[i][j] = fmaf(ar[i], br[j], acc[i][j]);
        }
    }

    const int crow0 = blockIdx.y * 128 + ty * 8;
    const int ccol0 = blockIdx.x * 128 + tx * 8;
    #pragma unroll
    for (int i = 0; i < 8; i++) {
        float* dst = Cc + (size_t)(crow0 + i) * C + ccol0;
        float4 o0 = make_float4(acc[i][0], acc[i][1], acc[i][2], acc[i][3]);
        float4 o1 = make_float4(acc[i][4], acc[i][5], acc[i][6], acc[i][7]);
        *(float4*)(dst)     = o0;
        *(float4*)(dst + 4) = o1;
    }
}

// ---------------- kernel 3: softmax over d of (invZ_c * B[c,:]), in place ----------------
__global__ void k_bsoftmax() {
    size_t row = blockIdx.x;  // n*C + c
    float4* br = (float4*)(g_B + row * (size_t)C);
    float iz = g_invZ[row];

    int t = threadIdx.x;                     // 128 threads, 4 values each
    float4 v4 = br[t];
    float v[4] = {v4.x * iz, v4.y * iz, v4.z * iz, v4.w * iz};
    float m = fmaxf(fmaxf(v[0], v[1]), fmaxf(v[2], v[3]));
    m = blockReduceMax(m);
    float s = 0.0f;
    #pragma unroll
    for (int j = 0; j < 4; j++) { v[j] = __expf(v[j] - m); s += v[j]; }
    s = blockReduceSum(s);
    float inv = 1.0f / s;
    br[t] = make_float4(v[0] * inv, v[1] * inv, v[2] * inv, v[3] * inv);
}

// ---------------- kernel 3b: w[n,d] = sum_c P[n,c,d] ----------------
__global__ void k_colsum() {
    int n = blockIdx.x;
    int d = blockIdx.y * 128 + threadIdx.x;
    const float* Bn = g_B + (size_t)n * C * C;
    float s0 = 0, s1 = 0, s2 = 0, s3 = 0;
    #pragma unroll 4
    for (int c = 0; c < C; c += 4) {
        s0 += Bn[(size_t)(c + 0) * C + d];
        s1 += Bn[(size_t)(c + 1) * C + d];
        s2 += Bn[(size_t)(c + 2) * C + d];
        s3 += Bn[(size_t)(c + 3) * C + d];
    }
    g_w[n * C + d] = (s0 + s1) + (s2 + s3);
}

// ---------------- kernel 4: out[n,s] = sum_d w[n,d] * x[n,d,s] ----------------
__global__ void k_out(const float* __restrict__ x, float* __restrict__ out) {
    int n = blockIdx.y;
    int s = blockIdx.x * 256 + threadIdx.x;
    __shared__ float ws[C];
    for (int i = threadIdx.x; i < C; i += 256) ws[i] = g_w[n * C + i];
    __syncthreads();
    if (s >= S) return;
    const float* fb = x + (size_t)n * C * S + s;
    float a0 = 0, a1 = 0, a2 = 0, a3 = 0;
    #pragma unroll 2
    for (int d = 0; d < C; d += 4) {
        a0 = fmaf(ws[d + 0], fb[(size_t)(d + 0) * S], a0);
        a1 = fmaf(ws[d + 1], fb[(size_t)(d + 1) * S], a1);
        a2 = fmaf(ws[d + 2], fb[(size_t)(d + 2) * S], a2);
        a3 = fmaf(ws[d + 3], fb[(size_t)(d + 3) * S], a3);
    }
    out[n * S + s] = (a0 + a1) + (a2 + a3);
}

extern "C" void kernel_launch(void* const* d_in, const int* in_sizes, int n_in,
                              void* d_out, int out_size) {
    const float* x = (const float*)d_in[0];
    float* out = (float*)d_out;

    k_rowexp<<<NB * C, 256>>>(x);

    dim3 g2(C / 128, C / 128, NB);   // (4,4,32)
    k_gemm<<<g2, 256>>>(x);

    k_bsoftmax<<<NB * C, 128>>>();

    dim3 g3(NB, C / 128);            // (32,4)
    k_colsum<<<g3, 128>>>();

    dim3 g4((S + 255) / 256, NB);    // (13,32)
    k_out<<<g4, 256>>>(x, out);
}

// round 3
// speedup vs baseline: 1.6741x; 1.6741x over previous
#include <cuda_runtime.h>
#include <cuda_bf16.h>
#include <math.h>
#include <stdint.h>

#define NB 32
#define C  512
#define S  3136   // 56*56
#define S4 (S/4)
#define BK 32
#define NITER (3 * (S / BK))   // 3 terms x 98 k-chunks = 294

// ---------------- scratch (device globals; no allocations allowed) ----------------
__device__ __nv_bfloat16 g_ehi[(size_t)NB * C * S];
__device__ __nv_bfloat16 g_elo[(size_t)NB * C * S];
__device__ __nv_bfloat16 g_xhi[(size_t)NB * C * S];
__device__ __nv_bfloat16 g_xlo[(size_t)NB * C * S];
__device__ float g_invZ[NB * C];
__device__ float g_B[(size_t)NB * C * C];
__device__ float g_w[NB * C];

__device__ __forceinline__ uint32_t smem_u32(const void* p) {
    uint32_t a;
    asm("{ .reg .u64 t; cvta.to.shared.u64 t, %1; cvt.u32.u64 %0, t; }" : "=r"(a) : "l"(p));
    return a;
}

// ---------------- block reductions ----------------
__device__ __forceinline__ float blockReduceMax(float v) {
    __shared__ float sh[32];
    int lane = threadIdx.x & 31, w = threadIdx.x >> 5;
    __syncthreads();
    #pragma unroll
    for (int o = 16; o; o >>= 1) v = fmaxf(v, __shfl_xor_sync(0xffffffffu, v, o));
    if (lane == 0) sh[w] = v;
    __syncthreads();
    int nw = (blockDim.x + 31) >> 5;
    if (w == 0) {
        v = (lane < nw) ? sh[lane] : -INFINITY;
        #pragma unroll
        for (int o = 16; o; o >>= 1) v = fmaxf(v, __shfl_xor_sync(0xffffffffu, v, o));
        if (lane == 0) sh[0] = v;
    }
    __syncthreads();
    return sh[0];
}
__device__ __forceinline__ float blockReduceSum(float v) {
    __shared__ float sh[32];
    int lane = threadIdx.x & 31, w = threadIdx.x >> 5;
    __syncthreads();
    #pragma unroll
    for (int o = 16; o; o >>= 1) v += __shfl_xor_sync(0xffffffffu, v, o);
    if (lane == 0) sh[w] = v;
    __syncthreads();
    int nw = (blockDim.x + 31) >> 5;
    if (w == 0) {
        v = (lane < nw) ? sh[lane] : 0.0f;
        #pragma unroll
        for (int o = 16; o; o >>= 1) v += __shfl_xor_sync(0xffffffffu, v, o);
        if (lane == 0) sh[0] = v;
    }
    __syncthreads();
    return sh[0];
}

// ---------------- split helpers ----------------
__device__ __forceinline__ uint32_t pack2bf(__nv_bfloat16 a, __nv_bfloat16 b) {
    return (uint32_t)__bfloat16_as_ushort(a) | ((uint32_t)__bfloat16_as_ushort(b) << 16);
}
__device__ __forceinline__ void split4(float4 v, uint2& hi, uint2& lo) {
    __nv_bfloat16 h0 = __float2bfloat16(v.x), h1 = __float2bfloat16(v.y);
    __nv_bfloat16 h2 = __float2bfloat16(v.z), h3 = __float2bfloat16(v.w);
    float l0 = v.x - __bfloat162float(h0), l1 = v.y - __bfloat162float(h1);
    float l2 = v.z - __bfloat162float(h2), l3 = v.w - __bfloat162float(h3);
    hi.x = pack2bf(h0, h1); hi.y = pack2bf(h2, h3);
    lo.x = pack2bf(__float2bfloat16(l0), __float2bfloat16(l1));
    lo.y = pack2bf(__float2bfloat16(l2), __float2bfloat16(l3));
}

// ---------------- kernel 1: softmax-exp row pass + hi/lo splits of e and x ----------------
__global__ void k_rowexp(const float* __restrict__ x) {
    size_t row = blockIdx.x;  // n*C + c
    const float4* xr = (const float4*)(x + row * S);
    uint2* xh = (uint2*)(g_xhi + row * S);
    uint2* xl = (uint2*)(g_xlo + row * S);
    uint2* eh = (uint2*)(g_ehi + row * S);
    uint2* el = (uint2*)(g_elo + row * S);

    float m = -INFINITY;
    for (int i = threadIdx.x; i < S4; i += blockDim.x) {
        float4 v = xr[i];
        m = fmaxf(m, fmaxf(fmaxf(v.x, v.y), fmaxf(v.z, v.w)));
    }
    m = blockReduceMax(m);

    float s = 0.0f;
    for (int i = threadIdx.x; i < S4; i += blockDim.x) {
        float4 v = xr[i];
        uint2 hi, lo;
        split4(v, hi, lo);
        xh[i] = hi; xl[i] = lo;
        float4 e;
        e.x = __expf(7.0f * (v.x - m));
        e.y = __expf(7.0f * (v.y - m));
        e.z = __expf(7.0f * (v.z - m));
        e.w = __expf(7.0f * (v.w - m));
        s += (e.x + e.y) + (e.z + e.w);
        split4(e, hi, lo);
        eh[i] = hi; el[i] = lo;
    }
    s = blockReduceSum(s);
    if (threadIdx.x == 0) g_invZ[row] = 1.0f / s;
}

// ---------------- kernel 2: warp-MMA batched GEMM  B[n] = E[n] @ X[n]^T ----------------
// 128x128 CTA tile, BK=32, 8 warps (4x2), each warp 32x64.
// 3-term split-bf16: Ehi*Xhi^T + Ehi*Xlo^T + Elo*Xhi^T, fp32 accumulate.
// SMEM tiles [128 rows][32 k] bf16 with row stride 40 elems (80B, ldmatrix conflict-free).
#define LDA 40
#define TILE_BYTES (128 * LDA * 2)   // 10240

__device__ __forceinline__ void cp16(uint32_t saddr, const void* gptr) {
    asm volatile("cp.async.cg.shared.global [%0], [%1], 16;" :: "r"(saddr), "l"(gptr) : "memory");
}

__global__ __launch_bounds__(256) void k_gemm_mma() {
    __shared__ __align__(16) unsigned char smA[2][TILE_BYTES];
    __shared__ __align__(16) unsigned char smB[2][TILE_BYTES];

    const int tid = threadIdx.x, lane = tid & 31, wid = tid >> 5;
    const int n = blockIdx.z, tm = blockIdx.y, tn = blockIdx.x;
    const int wm = wid >> 1, wn = wid & 1;   // warp tile: rows wm*32, cols wn*64

    const size_t nb = (size_t)n * C * S;
    // loader: each thread owns half a row (16 bf16 = 32B) of the 128x32 tile
    const int lr = tid >> 1;             // 0..127
    const int lc = (tid & 1) * 16;       // 0 or 16 (elems)
    const __nv_bfloat16* aT[3];
    const __nv_bfloat16* bT[3];
    {
        const size_t ao = nb + (size_t)(tm * 128 + lr) * S + lc;
        const size_t bo = nb + (size_t)(tn * 128 + lr) * S + lc;
        aT[0] = g_ehi + ao; aT[1] = g_ehi + ao; aT[2] = g_elo + ao;
        bT[0] = g_xhi + bo; bT[1] = g_xlo + bo; bT[2] = g_xhi + bo;
    }
    const uint32_t sDst = (uint32_t)(lr * (LDA * 2) + lc * 2);
    uint32_t aBase[2] = { smem_u32(smA[0]), smem_u32(smA[1]) };
    uint32_t bBase[2] = { smem_u32(smB[0]), smem_u32(smB[1]) };

    // ldmatrix per-lane offset (identical formula for A and B):
    // q = lane/8: matrices (rows+0,k0),(rows+8,k0),(rows+0,k8),(rows+8,k8)
    const int q = lane >> 3, r8 = lane & 7;
    const uint32_t laneOff = (uint32_t)((((q & 1) << 3) + r8) * (LDA * 2) + ((q >> 1) << 3) * 2);

    float acc[2][8][4];
    #pragma unroll
    for (int mi = 0; mi < 2; mi++)
        #pragma unroll
        for (int ni = 0; ni < 8; ni++)
            #pragma unroll
            for (int j = 0; j < 4; j++) acc[mi][ni][j] = 0.0f;

    auto issue = [&](int it) {
        const int t = it / 98;
        const int k0 = (it - t * 98) * BK;
        const int buf = it & 1;
        uint32_t sa = aBase[buf] + sDst;
        uint32_t sb = bBase[buf] + sDst;
        const __nv_bfloat16* ga = aT[t] + k0;
        const __nv_bfloat16* gb = bT[t] + k0;
        cp16(sa, ga);       cp16(sa + 16, ga + 8);
        cp16(sb, gb);       cp16(sb + 16, gb + 8);
        asm volatile("cp.async.commit_group;" ::: "memory");
    };

    issue(0);
    for (int it = 0; it < NITER; it++) {
        const int buf = it & 1;
        if (it + 1 < NITER) {
            issue(it + 1);
            asm volatile("cp.async.wait_group 1;" ::: "memory");
        } else {
            asm volatile("cp.async.wait_group 0;" ::: "memory");
        }
        __syncthreads();

        const uint32_t aB = aBase[buf] + (uint32_t)(wm * 32) * (LDA * 2) + laneOff;
        const uint32_t bB = bBase[buf] + (uint32_t)(wn * 64) * (LDA * 2) + laneOff;
        #pragma unroll
        for (int kk = 0; kk < 2; kk++) {
            uint32_t a[2][4], b[4][4];
            #pragma unroll
            for (int mi = 0; mi < 2; mi++) {
                asm volatile("ldmatrix.sync.aligned.m8n8.x4.shared.b16 {%0,%1,%2,%3}, [%4];"
                    : "=r"(a[mi][0]), "=r"(a[mi][1]), "=r"(a[mi][2]), "=r"(a[mi][3])
                    : "r"(aB + (uint32_t)(mi * 16) * (LDA * 2) + (uint32_t)kk * 32));
            }
            #pragma unroll
            for (int p = 0; p < 4; p++) {
                asm volatile("ldmatrix.sync.aligned.m8n8.x4.shared.b16 {%0,%1,%2,%3}, [%4];"
                    : "=r"(b[p][0]), "=r"(b[p][1]), "=r"(b[p][2]), "=r"(b[p][3])
                    : "r"(bB + (uint32_t)(p * 16) * (LDA * 2) + (uint32_t)kk * 32));
            }
            #pragma unroll
            for (int mi = 0; mi < 2; mi++) {
                #pragma unroll
                for (int p = 0; p < 4; p++) {
                    // tile n=2p uses {b0,b2}; tile n=2p+1 uses {b1,b3}
                    asm volatile(
                        "mma.sync.aligned.m16n8k16.row.col.f32.bf16.bf16.f32 "
                        "{%0,%1,%2,%3},{%4,%5,%6,%7},{%8,%9},{%0,%1,%2,%3};"
                        : "+f"(acc[mi][2*p][0]), "+f"(acc[mi][2*p][1]),
                          "+f"(acc[mi][2*p][2]), "+f"(acc[mi][2*p][3])
                        : "r"(a[mi][0]), "r"(a[mi][1]), "r"(a[mi][2]), "r"(a[mi][3]),
                          "r"(b[p][0]), "r"(b[p][2]));
                    asm volatile(
                        "mma.sync.aligned.m16n8k16.row.col.f32.bf16.bf16.f32 "
                        "{%0,%1,%2,%3},{%4,%5,%6,%7},{%8,%9},{%0,%1,%2,%3};"
                        : "+f"(acc[mi][2*p+1][0]), "+f"(acc[mi][2*p+1][1]),
                          "+f"(acc[mi][2*p+1][2]), "+f"(acc[mi][2*p+1][3])
                        : "r"(a[mi][0]), "r"(a[mi][1]), "r"(a[mi][2]), "r"(a[mi][3]),
                          "r"(b[p][1]), "r"(b[p][3]));
                }
            }
        }
        __syncthreads();
    }

    // epilogue: acc -> g_B
    float* Cn = g_B + (size_t)n * C * C;
    const int mrow0 = tm * 128 + wm * 32 + (lane >> 2);
    const int ncol0 = tn * 128 + wn * 64 + (lane & 3) * 2;
    #pragma unroll
    for (int mi = 0; mi < 2; mi++) {
        #pragma unroll
        for (int ni = 0; ni < 8; ni++) {
            const int r = mrow0 + mi * 16;
            const int cc = ncol0 + ni * 8;
            *(float2*)&Cn[(size_t)r * C + cc]       = make_float2(acc[mi][ni][0], acc[mi][ni][1]);
            *(float2*)&Cn[(size_t)(r + 8) * C + cc] = make_float2(acc[mi][ni][2], acc[mi][ni][3]);
        }
    }
}

// ---------------- kernel 3: softmax over d of (invZ_c * B[c,:]), in place ----------------
__global__ void k_bsoftmax() {
    size_t row = blockIdx.x;  // n*C + c
    float4* br = (float4*)(g_B + row * (size_t)C);
    float iz = g_invZ[row];
    int t = threadIdx.x;      // 128 threads, 4 values each
    float4 v4 = br[t];
    float v[4] = {v4.x * iz, v4.y * iz, v4.z * iz, v4.w * iz};
    float m = fmaxf(fmaxf(v[0], v[1]), fmaxf(v[2], v[3]));
    m = blockReduceMax(m);
    float s = 0.0f;
    #pragma unroll
    for (int j = 0; j < 4; j++) { v[j] = __expf(v[j] - m); s += v[j]; }
    s = blockReduceSum(s);
    float inv = 1.0f / s;
    br[t] = make_float4(v[0] * inv, v[1] * inv, v[2] * inv, v[3] * inv);
}

// ---------------- kernel 3b: w[n,d] = sum_c P[n,c,d] ----------------
__global__ void k_colsum() {
    int n = blockIdx.x;
    int dl = threadIdx.x & 127;
    int q  = threadIdx.x >> 7;    // 0..3
    int d  = blockIdx.y * 128 + dl;
    const float* Bn = g_B + (size_t)n * C * C + d;
    float s = 0.0f;
    #pragma unroll 8
    for (int c = q * 128; c < q * 128 + 128; c++) s += Bn[(size_t)c * C];
    __shared__ float sh[4][128];
    sh[q][dl] = s;
    __syncthreads();
    if (q == 0) g_w[n * C + d] = (sh[0][dl] + sh[1][dl]) + (sh[2][dl] + sh[3][dl]);
}

// ---------------- kernel 4: out[n,s] = sum_d w[n,d] * x[n,d,s] ----------------
__global__ void k_out(const float* __restrict__ x, float* __restrict__ out) {
    int n = blockIdx.y;
    int s = blockIdx.x * 256 + threadIdx.x;
    __shared__ float ws[C];
    for (int i = threadIdx.x; i < C; i += 256) ws[i] = g_w[n * C + i];
    __syncthreads();
    if (s >= S) return;
    const float* fb = x + (size_t)n * C * S + s;
    float a0 = 0, a1 = 0, a2 = 0, a3 = 0;
    #pragma unroll 2
    for (int d = 0; d < C; d += 4) {
        a0 = fmaf(ws[d + 0], fb[(size_t)(d + 0) * S], a0);
        a1 = fmaf(ws[d + 1], fb[(size_t)(d + 1) * S], a1);
        a2 = fmaf(ws[d + 2], fb[(size_t)(d + 2) * S], a2);
        a3 = fmaf(ws[d + 3], fb[(size_t)(d + 3) * S], a3);
    }
    out[n * S + s] = (a0 + a1) + (a2 + a3);
}

extern "C" void kernel_launch(void* const* d_in, const int* in_sizes, int n_in,
                              void* d_out, int out_size) {
    const float* x = (const float*)d_in[0];
    float* out = (float*)d_out;

    k_rowexp<<<NB * C, 256>>>(x);

    dim3 g2(C / 128, C / 128, NB);   // (4,4,32) = 512 CTAs
    k_gemm_mma<<<g2, 256>>>();

    k_bsoftmax<<<NB * C, 128>>>();

    dim3 g3(NB, C / 128);            // (32,4)
    k_colsum<<<g3, 512>>>();

    dim3 g4((S + 255) / 256, NB);    // (13,32)
    k_out<<<g4, 256>>>(x, out);
}

// round 4
// speedup vs baseline: 2.7586x; 1.6479x over previous
#include <cuda_runtime.h>
#include <cuda_fp16.h>
#include <math.h>
#include <stdint.h>

#define NB 32
#define C  512
#define S  3136   // 56*56
#define S4 (S/4)
#define BK 32
#define NCHUNK (S / BK)   // 98

// ---------------- scratch (device globals; no allocations allowed) ----------------
__device__ __half g_eh[(size_t)NB * C * S];   // fp16(4096 * exp(7*(x - rowmax)))
__device__ float g_invZ[NB * C];              // 1 / sum(e')
__device__ float g_B[(size_t)NB * C * C];
__device__ float g_w[NB * C];

__device__ __forceinline__ uint32_t smem_u32(const void* p) {
    uint32_t a;
    asm("{ .reg .u64 t; cvta.to.shared.u64 t, %1; cvt.u32.u64 %0, t; }" : "=r"(a) : "l"(p));
    return a;
}

// ---------------- block reductions ----------------
__device__ __forceinline__ float blockReduceMax(float v) {
    __shared__ float sh[32];
    int lane = threadIdx.x & 31, w = threadIdx.x >> 5;
    __syncthreads();
    #pragma unroll
    for (int o = 16; o; o >>= 1) v = fmaxf(v, __shfl_xor_sync(0xffffffffu, v, o));
    if (lane == 0) sh[w] = v;
    __syncthreads();
    int nw = (blockDim.x + 31) >> 5;
    if (w == 0) {
        v = (lane < nw) ? sh[lane] : -INFINITY;
        #pragma unroll
        for (int o = 16; o; o >>= 1) v = fmaxf(v, __shfl_xor_sync(0xffffffffu, v, o));
        if (lane == 0) sh[0] = v;
    }
    __syncthreads();
    return sh[0];
}
__device__ __forceinline__ float blockReduceSum(float v) {
    __shared__ float sh[32];
    int lane = threadIdx.x & 31, w = threadIdx.x >> 5;
    __syncthreads();
    #pragma unroll
    for (int o = 16; o; o >>= 1) v += __shfl_xor_sync(0xffffffffu, v, o);
    if (lane == 0) sh[w] = v;
    __syncthreads();
    int nw = (blockDim.x + 31) >> 5;
    if (w == 0) {
        v = (lane < nw) ? sh[lane] : 0.0f;
        #pragma unroll
        for (int o = 16; o; o >>= 1) v += __shfl_xor_sync(0xffffffffu, v, o);
        if (lane == 0) sh[0] = v;
    }
    __syncthreads();
    return sh[0];
}

// ---------------- kernel 1: rowmax + scaled exp -> fp16 ----------------
__global__ void k_rowexp(const float* __restrict__ x) {
    size_t row = blockIdx.x;  // n*C + c
    const float4* xr = (const float4*)(x + row * S);
    uint2* er = (uint2*)(g_eh + row * S);   // 4 halves per uint2

    float m = -INFINITY;
    for (int i = threadIdx.x; i < S4; i += blockDim.x) {
        float4 v = xr[i];
        m = fmaxf(m, fmaxf(fmaxf(v.x, v.y), fmaxf(v.z, v.w)));
    }
    m = blockReduceMax(m);

    const float k = 10.098865286222744f;  // 7/ln(2)
    float s = 0.0f;
    for (int i = threadIdx.x; i < S4; i += blockDim.x) {
        float4 v = xr[i];
        float e0 = exp2f(fmaf(k, v.x - m, 12.0f));   // 4096 * exp(7*(x-m))
        float e1 = exp2f(fmaf(k, v.y - m, 12.0f));
        float e2 = exp2f(fmaf(k, v.z - m, 12.0f));
        float e3 = exp2f(fmaf(k, v.w - m, 12.0f));
        s += (e0 + e1) + (e2 + e3);
        __half2 h01 = __halves2half2(__float2half_rn(e0), __float2half_rn(e1));
        __half2 h23 = __halves2half2(__float2half_rn(e2), __float2half_rn(e3));
        uint2 o;
        o.x = *(uint32_t*)&h01;
        o.y = *(uint32_t*)&h23;
        er[i] = o;
    }
    s = blockReduceSum(s);
    if (threadIdx.x == 0) g_invZ[row] = 1.0f / s;
}

// ---------------- kernel 2: warp-MMA batched GEMM  B[n] = E[n] @ X[n]^T ----------------
// 128x128 CTA tile, BK=32, 8 warps (4x2), each warp 32x64.
// A = fp16 e (pre-split in gmem); X split hi/lo fp16 on the fly in the loader.
// Both terms (A*Xh^T and A*Xl^T) accumulate into one fp32 acc.
#define LDA 40
#define TILE_B (128 * LDA * 2)        // 10240 bytes per tile
#define STAGE_B (3 * TILE_B)          // A, Bh, Bl
#define SMEM_TOTAL (2 * STAGE_B)      // 61440

__global__ __launch_bounds__(256) void k_gemm_mma(const float* __restrict__ x) {
    extern __shared__ __align__(16) unsigned char sm[];

    const int tid = threadIdx.x, lane = tid & 31, wid = tid >> 5;
    const int n = blockIdx.z, tm = blockIdx.y, tn = blockIdx.x;
    const int wm = wid >> 1, wn = wid & 1;   // warp tile: rows wm*32, cols wn*64

    const size_t nb = (size_t)n * C * S;
    const int lr = tid >> 1;             // 0..127
    const int lc = (tid & 1) * 16;       // 0 or 16 (elems)
    const __half* Aptr = g_eh + nb + (size_t)(tm * 128 + lr) * S + lc;
    const float*  Xptr = x    + nb + (size_t)(tn * 128 + lr) * S + lc;
    const uint32_t sRow = (uint32_t)(lr * (LDA * 2) + lc * 2);
    const uint32_t smBase = smem_u32(sm);

    const int q = lane >> 3, r8 = lane & 7;
    const uint32_t laneOff = (uint32_t)((((q & 1) << 3) + r8) * (LDA * 2) + ((q >> 1) << 3) * 2);

    float acc[2][8][4];
    #pragma unroll
    for (int mi = 0; mi < 2; mi++)
        #pragma unroll
        for (int ni = 0; ni < 8; ni++)
            #pragma unroll
            for (int j = 0; j < 4; j++) acc[mi][ni][j] = 0.0f;

    uint4 ra0, ra1, rx0, rx1, rx2, rx3;

    auto ldg = [&](int it) {
        const int k0 = it * BK;
        const __half* ga = Aptr + k0;
        const float*  gx = Xptr + k0;
        ra0 = *(const uint4*)(ga);
        ra1 = *(const uint4*)(ga + 8);
        rx0 = *(const uint4*)(gx);
        rx1 = *(const uint4*)(gx + 4);
        rx2 = *(const uint4*)(gx + 8);
        rx3 = *(const uint4*)(gx + 12);
    };

    auto splitq = [](uint4 v, uint32_t& hi, uint32_t& lo) {
        float f0 = __uint_as_float(v.x), f1 = __uint_as_float(v.y);
        float f2 = __uint_as_float(v.z), f3 = __uint_as_float(v.w);
        __half h0 = __float2half_rn(f0), h1 = __float2half_rn(f1);
        __half h2 = __float2half_rn(f2), h3 = __float2half_rn(f3);
        __half l0 = __float2half_rn(f0 - __half2float(h0));
        __half l1 = __float2half_rn(f1 - __half2float(h1));
        __half l2 = __float2half_rn(f2 - __half2float(h2));
        __half l3 = __float2half_rn(f3 - __half2float(h3));
        __half2 hh = __halves2half2(h0, h1); uint32_t u0 = *(uint32_t*)&hh;
        __half2 hh2 = __halves2half2(h2, h3); uint32_t u1 = *(uint32_t*)&hh2;
        hi = 0; // dummy init (set below)
        // pack into two 32-bit words -> caller assembles uint4 pairs
        hi = u0; lo = u1;   // NOTE: hi here = halves(h0,h1), lo = halves(h2,h3)
    };
    (void)splitq;

    auto sts = [&](int buf) {
        unsigned char* st = sm + buf * STAGE_B;
        *(uint4*)(st + sRow)      = ra0;
        *(uint4*)(st + sRow + 16) = ra1;
        // convert 16 floats -> hi/lo halves
        uint32_t hi[8], lo[8];
        uint4 rx[4] = {rx0, rx1, rx2, rx3};
        #pragma unroll
        for (int j = 0; j < 4; j++) {
            float f0 = __uint_as_float(rx[j].x), f1 = __uint_as_float(rx[j].y);
            float f2 = __uint_as_float(rx[j].z), f3 = __uint_as_float(rx[j].w);
            __half h0 = __float2half_rn(f0), h1 = __float2half_rn(f1);
            __half h2 = __float2half_rn(f2), h3 = __float2half_rn(f3);
            __half l0 = __float2half_rn(f0 - __half2float(h0));
            __half l1 = __float2half_rn(f1 - __half2float(h1));
            __half l2 = __float2half_rn(f2 - __half2float(h2));
            __half l3 = __float2half_rn(f3 - __half2float(h3));
            __half2 a = __halves2half2(h0, h1); hi[2*j]   = *(uint32_t*)&a;
            __half2 b = __halves2half2(h2, h3); hi[2*j+1] = *(uint32_t*)&b;
            __half2 c = __halves2half2(l0, l1); lo[2*j]   = *(uint32_t*)&c;
            __half2 d = __halves2half2(l2, l3); lo[2*j+1] = *(uint32_t*)&d;
        }
        *(uint4*)(st + TILE_B + sRow)      = make_uint4(hi[0], hi[1], hi[2], hi[3]);
        *(uint4*)(st + TILE_B + sRow + 16) = make_uint4(hi[4], hi[5], hi[6], hi[7]);
        *(uint4*)(st + 2*TILE_B + sRow)      = make_uint4(lo[0], lo[1], lo[2], lo[3]);
        *(uint4*)(st + 2*TILE_B + sRow + 16) = make_uint4(lo[4], lo[5], lo[6], lo[7]);
    };

    ldg(0);
    for (int it = 0; it < NCHUNK; it++) {
        const int buf = it & 1;
        sts(buf);
        __syncthreads();
        if (it + 1 < NCHUNK) ldg(it + 1);

        const uint32_t base = smBase + (uint32_t)buf * STAGE_B;
        const uint32_t aB  = base + (uint32_t)(wm * 32) * (LDA * 2) + laneOff;
        const uint32_t bBh = base + TILE_B   + (uint32_t)(wn * 64) * (LDA * 2) + laneOff;
        const uint32_t bBl = base + 2*TILE_B + (uint32_t)(wn * 64) * (LDA * 2) + laneOff;

        #pragma unroll
        for (int kk = 0; kk < 2; kk++) {
            uint32_t a[2][4], bh[4][4], bl[4][4];
            #pragma unroll
            for (int mi = 0; mi < 2; mi++) {
                asm volatile("ldmatrix.sync.aligned.m8n8.x4.shared.b16 {%0,%1,%2,%3}, [%4];"
                    : "=r"(a[mi][0]), "=r"(a[mi][1]), "=r"(a[mi][2]), "=r"(a[mi][3])
                    : "r"(aB + (uint32_t)(mi * 16) * (LDA * 2) + (uint32_t)kk * 32));
            }
            #pragma unroll
            for (int p = 0; p < 4; p++) {
                asm volatile("ldmatrix.sync.aligned.m8n8.x4.shared.b16 {%0,%1,%2,%3}, [%4];"
                    : "=r"(bh[p][0]), "=r"(bh[p][1]), "=r"(bh[p][2]), "=r"(bh[p][3])
                    : "r"(bBh + (uint32_t)(p * 16) * (LDA * 2) + (uint32_t)kk * 32));
                asm volatile("ldmatrix.sync.aligned.m8n8.x4.shared.b16 {%0,%1,%2,%3}, [%4];"
                    : "=r"(bl[p][0]), "=r"(bl[p][1]), "=r"(bl[p][2]), "=r"(bl[p][3])
                    : "r"(bBl + (uint32_t)(p * 16) * (LDA * 2) + (uint32_t)kk * 32));
            }
            #pragma unroll
            for (int mi = 0; mi < 2; mi++) {
                #pragma unroll
                for (int p = 0; p < 4; p++) {
                    asm volatile(
                        "mma.sync.aligned.m16n8k16.row.col.f32.f16.f16.f32 "
                        "{%0,%1,%2,%3},{%4,%5,%6,%7},{%8,%9},{%0,%1,%2,%3};"
                        : "+f"(acc[mi][2*p][0]), "+f"(acc[mi][2*p][1]),
                          "+f"(acc[mi][2*p][2]), "+f"(acc[mi][2*p][3])
                        : "r"(a[mi][0]), "r"(a[mi][1]), "r"(a[mi][2]), "r"(a[mi][3]),
                          "r"(bh[p][0]), "r"(bh[p][2]));
                    asm volatile(
                        "mma.sync.aligned.m16n8k16.row.col.f32.f16.f16.f32 "
                        "{%0,%1,%2,%3},{%4,%5,%6,%7},{%8,%9},{%0,%1,%2,%3};"
                        : "+f"(acc[mi][2*p+1][0]), "+f"(acc[mi][2*p+1][1]),
                          "+f"(acc[mi][2*p+1][2]), "+f"(acc[mi][2*p+1][3])
                        : "r"(a[mi][0]), "r"(a[mi][1]), "r"(a[mi][2]), "r"(a[mi][3]),
                          "r"(bh[p][1]), "r"(bh[p][3]));
                    asm volatile(
                        "mma.sync.aligned.m16n8k16.row.col.f32.f16.f16.f32 "
                        "{%0,%1,%2,%3},{%4,%5,%6,%7},{%8,%9},{%0,%1,%2,%3};"
                        : "+f"(acc[mi][2*p][0]), "+f"(acc[mi][2*p][1]),
                          "+f"(acc[mi][2*p][2]), "+f"(acc[mi][2*p][3])
                        : "r"(a[mi][0]), "r"(a[mi][1]), "r"(a[mi][2]), "r"(a[mi][3]),
                          "r"(bl[p][0]), "r"(bl[p][2]));
                    asm volatile(
                        "mma.sync.aligned.m16n8k16.row.col.f32.f16.f16.f32 "
                        "{%0,%1,%2,%3},{%4,%5,%6,%7},{%8,%9},{%0,%1,%2,%3};"
                        : "+f"(acc[mi][2*p+1][0]), "+f"(acc[mi][2*p+1][1]),
                          "+f"(acc[mi][2*p+1][2]), "+f"(acc[mi][2*p+1][3])
                        : "r"(a[mi][0]), "r"(a[mi][1]), "r"(a[mi][2]), "r"(a[mi][3]),
                          "r"(bl[p][1]), "r"(bl[p][3]));
                }
            }
        }
        __syncthreads();
    }

    // epilogue: acc -> g_B
    float* Cn = g_B + (size_t)n * C * C;
    const int mrow0 = tm * 128 + wm * 32 + (lane >> 2);
    const int ncol0 = tn * 128 + wn * 64 + (lane & 3) * 2;
    #pragma unroll
    for (int mi = 0; mi < 2; mi++) {
        #pragma unroll
        for (int ni = 0; ni < 8; ni++) {
            const int r = mrow0 + mi * 16;
            const int cc = ncol0 + ni * 8;
            *(float2*)&Cn[(size_t)r * C + cc]       = make_float2(acc[mi][ni][0], acc[mi][ni][1]);
            *(float2*)&Cn[(size_t)(r + 8) * C + cc] = make_float2(acc[mi][ni][2], acc[mi][ni][3]);
        }
    }
}

// ---------------- kernel 3: softmax over d of (invZ_c * B[c,:]), in place ----------------
__global__ void k_bsoftmax() {
    size_t row = blockIdx.x;  // n*C + c
    float4* br = (float4*)(g_B + row * (size_t)C);
    float iz = g_invZ[row];
    int t = threadIdx.x;      // 128 threads, 4 values each
    float4 v4 = br[t];
    float v[4] = {v4.x * iz, v4.y * iz, v4.z * iz, v4.w * iz};
    float m = fmaxf(fmaxf(v[0], v[1]), fmaxf(v[2], v[3]));
    m = blockReduceMax(m);
    float s = 0.0f;
    #pragma unroll
    for (int j = 0; j < 4; j++) { v[j] = __expf(v[j] - m); s += v[j]; }
    s = blockReduceSum(s);
    float inv = 1.0f / s;
    br[t] = make_float4(v[0] * inv, v[1] * inv, v[2] * inv, v[3] * inv);
}

// ---------------- kernel 3b: w[n,d] = sum_c P[n,c,d] ----------------
__global__ void k_colsum() {
    int n = blockIdx.x;
    int dl = threadIdx.x & 127;
    int q  = threadIdx.x >> 7;    // 0..3
    int d  = blockIdx.y * 128 + dl;
    const float* Bn = g_B + (size_t)n * C * C + d;
    float s = 0.0f;
    #pragma unroll 8
    for (int c = q * 128; c < q * 128 + 128; c++) s += Bn[(size_t)c * C];
    __shared__ float sh[4][128];
    sh[q][dl] = s;
    __syncthreads();
    if (q == 0) g_w[n * C + d] = (sh[0][dl] + sh[1][dl]) + (sh[2][dl] + sh[3][dl]);
}

// ---------------- kernel 4: out[n,s] = sum_d w[n,d] * x[n,d,s] ----------------
__global__ void k_out(const float* __restrict__ x, float* __restrict__ out) {
    int n = blockIdx.y;
    int s = blockIdx.x * 256 + threadIdx.x;
    __shared__ float ws[C];
    for (int i = threadIdx.x; i < C; i += 256) ws[i] = g_w[n * C + i];
    __syncthreads();
    if (s >= S) return;
    const float* fb = x + (size_t)n * C * S + s;
    float a0 = 0, a1 = 0, a2 = 0, a3 = 0;
    #pragma unroll 2
    for (int d = 0; d < C; d += 4) {
        a0 = fmaf(ws[d + 0], fb[(size_t)(d + 0) * S], a0);
        a1 = fmaf(ws[d + 1], fb[(size_t)(d + 1) * S], a1);
        a2 = fmaf(ws[d + 2], fb[(size_t)(d + 2) * S], a2);
        a3 = fmaf(ws[d + 3], fb[(size_t)(d + 3) * S], a3);
    }
    out[n * S + s] = (a0 + a1) + (a2 + a3);
}

extern "C" void kernel_launch(void* const* d_in, const int* in_sizes, int n_in,
                              void* d_out, int out_size) {
    const float* x = (const float*)d_in[0];
    float* out = (float*)d_out;

    cudaFuncSetAttribute(k_gemm_mma, cudaFuncAttributeMaxDynamicSharedMemorySize, SMEM_TOTAL);

    k_rowexp<<<NB * C, 256>>>(x);

    dim3 g2(C / 128, C / 128, NB);   // (4,4,32) = 512 CTAs
    k_gemm_mma<<<g2, 256, SMEM_TOTAL>>>(x);

    k_bsoftmax<<<NB * C, 128>>>();

    dim3 g3(NB, C / 128);            // (32,4)
    k_colsum<<<g3, 512>>>();

    dim3 g4((S + 255) / 256, NB);    // (13,32)
    k_out<<<g4, 256>>>(x, out);
}

// round 6
// speedup vs baseline: 3.4483x; 1.2500x over previous
#include <cuda_runtime.h>
#include <cuda_fp16.h>
#include <math.h>
#include <stdint.h>

#define NB 32
#define C  512
#define S  3136   // 56*56
#define S4 (S/4)
#define BK 32
#define NCHUNK (S / BK)   // 98

// ---------------- scratch (device globals; no allocations allowed) ----------------
__device__ __half g_eh[(size_t)NB * C * S];   // fp16(4096 * exp(7*(x - rowmax)))
__device__ float g_invZ[NB * C];              // 1 / sum(e')
__device__ float g_B[(size_t)NB * C * C];
__device__ float g_w[NB * C];

__device__ __forceinline__ uint32_t smem_u32(const void* p) {
    uint32_t a;
    asm("{ .reg .u64 t; cvta.to.shared.u64 t, %1; cvt.u32.u64 %0, t; }" : "=r"(a) : "l"(p));
    return a;
}

// ---------------- block reductions ----------------
__device__ __forceinline__ float blockReduceMax(float v) {
    __shared__ float sh[32];
    int lane = threadIdx.x & 31, w = threadIdx.x >> 5;
    __syncthreads();
    #pragma unroll
    for (int o = 16; o; o >>= 1) v = fmaxf(v, __shfl_xor_sync(0xffffffffu, v, o));
    if (lane == 0) sh[w] = v;
    __syncthreads();
    int nw = (blockDim.x + 31) >> 5;
    if (w == 0) {
        v = (lane < nw) ? sh[lane] : -INFINITY;
        #pragma unroll
        for (int o = 16; o; o >>= 1) v = fmaxf(v, __shfl_xor_sync(0xffffffffu, v, o));
        if (lane == 0) sh[0] = v;
    }
    __syncthreads();
    return sh[0];
}
__device__ __forceinline__ float blockReduceSum(float v) {
    __shared__ float sh[32];
    int lane = threadIdx.x & 31, w = threadIdx.x >> 5;
    __syncthreads();
    #pragma unroll
    for (int o = 16; o; o >>= 1) v += __shfl_xor_sync(0xffffffffu, v, o);
    if (lane == 0) sh[w] = v;
    __syncthreads();
    int nw = (blockDim.x + 31) >> 5;
    if (w == 0) {
        v = (lane < nw) ? sh[lane] : 0.0f;
        #pragma unroll
        for (int o = 16; o; o >>= 1) v += __shfl_xor_sync(0xffffffffu, v, o);
        if (lane == 0) sh[0] = v;
    }
    __syncthreads();
    return sh[0];
}

// ---------------- kernel 1: rowmax + scaled exp -> fp16 ----------------
__global__ void k_rowexp(const float* __restrict__ x) {
    size_t row = blockIdx.x;  // n*C + c
    const float4* xr = (const float4*)(x + row * S);
    uint2* er = (uint2*)(g_eh + row * S);   // 4 halves per uint2

    float m = -INFINITY;
    for (int i = threadIdx.x; i < S4; i += blockDim.x) {
        float4 v = xr[i];
        m = fmaxf(m, fmaxf(fmaxf(v.x, v.y), fmaxf(v.z, v.w)));
    }
    m = blockReduceMax(m);

    const float k = 10.098865286222744f;  // 7/ln(2)
    float s = 0.0f;
    for (int i = threadIdx.x; i < S4; i += blockDim.x) {
        float4 v = xr[i];
        float e0 = exp2f(fmaf(k, v.x - m, 12.0f));   // 4096 * exp(7*(x-m))
        float e1 = exp2f(fmaf(k, v.y - m, 12.0f));
        float e2 = exp2f(fmaf(k, v.z - m, 12.0f));
        float e3 = exp2f(fmaf(k, v.w - m, 12.0f));
        s += (e0 + e1) + (e2 + e3);
        __half2 h01 = __halves2half2(__float2half_rn(e0), __float2half_rn(e1));
        __half2 h23 = __halves2half2(__float2half_rn(e2), __float2half_rn(e3));
        uint2 o;
        o.x = *(uint32_t*)&h01;
        o.y = *(uint32_t*)&h23;
        er[i] = o;
    }
    s = blockReduceSum(s);
    if (threadIdx.x == 0) g_invZ[row] = 1.0f / s;
}

// ---------------- kernel 2: warp-MMA batched GEMM  B[n] = E[n] @ Xh[n]^T ----------------
// 128x128 CTA tile, BK=32, 8 warps (4x2), each warp 32x64; single fp16 term.
// A = fp16 e (pre-computed); X converted fp32->fp16 on the fly in the loader.
#define LDA 40
#define TILE_B (128 * LDA * 2)        // 10240 bytes per tile
#define STAGE_B (2 * TILE_B)          // A, Bh
#define SMEM_TOTAL (2 * STAGE_B)      // 40960

__global__ __launch_bounds__(256, 2) void k_gemm_mma(const float* __restrict__ x) {
    extern __shared__ __align__(16) unsigned char sm[];

    const int tid = threadIdx.x, lane = tid & 31, wid = tid >> 5;
    const int n = blockIdx.z, tm = blockIdx.y, tn = blockIdx.x;
    const int wm = wid >> 1, wn = wid & 1;   // warp tile: rows wm*32, cols wn*64

    const size_t nb = (size_t)n * C * S;
    const int lr = tid >> 1;             // 0..127
    const int lc = (tid & 1) * 16;       // 0 or 16 (elems)
    const __half* Aptr = g_eh + nb + (size_t)(tm * 128 + lr) * S + lc;
    const float*  Xptr = x    + nb + (size_t)(tn * 128 + lr) * S + lc;
    const uint32_t sRow = (uint32_t)(lr * (LDA * 2) + lc * 2);
    const uint32_t smBase = smem_u32(sm);

    const int q = lane >> 3, r8 = lane & 7;
    const uint32_t laneOff = (uint32_t)((((q & 1) << 3) + r8) * (LDA * 2) + ((q >> 1) << 3) * 2);

    float acc[2][8][4];
    #pragma unroll
    for (int mi = 0; mi < 2; mi++)
        #pragma unroll
        for (int ni = 0; ni < 8; ni++)
            #pragma unroll
            for (int j = 0; j < 4; j++) acc[mi][ni][j] = 0.0f;

    uint4 ra0, ra1, rx0, rx1, rx2, rx3;

    auto ldg = [&](int it) {
        const int k0 = it * BK;
        const __half* ga = Aptr + k0;
        const float*  gx = Xptr + k0;
        ra0 = *(const uint4*)(ga);
        ra1 = *(const uint4*)(ga + 8);
        rx0 = *(const uint4*)(gx);
        rx1 = *(const uint4*)(gx + 4);
        rx2 = *(const uint4*)(gx + 8);
        rx3 = *(const uint4*)(gx + 12);
    };

    auto sts = [&](int buf) {
        unsigned char* st = sm + buf * STAGE_B;
        *(uint4*)(st + sRow)      = ra0;
        *(uint4*)(st + sRow + 16) = ra1;
        uint32_t hi[8];
        uint4 rx[4] = {rx0, rx1, rx2, rx3};
        #pragma unroll
        for (int j = 0; j < 4; j++) {
            float f0 = __uint_as_float(rx[j].x), f1 = __uint_as_float(rx[j].y);
            float f2 = __uint_as_float(rx[j].z), f3 = __uint_as_float(rx[j].w);
            __half2 a = __halves2half2(__float2half_rn(f0), __float2half_rn(f1));
            __half2 b = __halves2half2(__float2half_rn(f2), __float2half_rn(f3));
            hi[2*j]   = *(uint32_t*)&a;
            hi[2*j+1] = *(uint32_t*)&b;
        }
        *(uint4*)(st + TILE_B + sRow)      = make_uint4(hi[0], hi[1], hi[2], hi[3]);
        *(uint4*)(st + TILE_B + sRow + 16) = make_uint4(hi[4], hi[5], hi[6], hi[7]);
    };

    ldg(0);
    for (int it = 0; it < NCHUNK; it++) {
        const int buf = it & 1;
        sts(buf);
        __syncthreads();
        if (it + 1 < NCHUNK) ldg(it + 1);

        const uint32_t base = smBase + (uint32_t)buf * STAGE_B;
        const uint32_t aB  = base + (uint32_t)(wm * 32) * (LDA * 2) + laneOff;
        const uint32_t bBh = base + TILE_B + (uint32_t)(wn * 64) * (LDA * 2) + laneOff;

        #pragma unroll
        for (int kk = 0; kk < 2; kk++) {
            uint32_t a[2][4], bh[4][4];
            #pragma unroll
            for (int mi = 0; mi < 2; mi++) {
                asm volatile("ldmatrix.sync.aligned.m8n8.x4.shared.b16 {%0,%1,%2,%3}, [%4];"
                    : "=r"(a[mi][0]), "=r"(a[mi][1]), "=r"(a[mi][2]), "=r"(a[mi][3])
                    : "r"(aB + (uint32_t)(mi * 16) * (LDA * 2) + (uint32_t)kk * 32));
            }
            #pragma unroll
            for (int p = 0; p < 4; p++) {
                asm volatile("ldmatrix.sync.aligned.m8n8.x4.shared.b16 {%0,%1,%2,%3}, [%4];"
                    : "=r"(bh[p][0]), "=r"(bh[p][1]), "=r"(bh[p][2]), "=r"(bh[p][3])
                    : "r"(bBh + (uint32_t)(p * 16) * (LDA * 2) + (uint32_t)kk * 32));
            }
            #pragma unroll
            for (int mi = 0; mi < 2; mi++) {
                #pragma unroll
                for (int p = 0; p < 4; p++) {
                    asm volatile(
                        "mma.sync.aligned.m16n8k16.row.col.f32.f16.f16.f32 "
                        "{%0,%1,%2,%3},{%4,%5,%6,%7},{%8,%9},{%0,%1,%2,%3};"
                        : "+f"(acc[mi][2*p][0]), "+f"(acc[mi][2*p][1]),
                          "+f"(acc[mi][2*p][2]), "+f"(acc[mi][2*p][3])
                        : "r"(a[mi][0]), "r"(a[mi][1]), "r"(a[mi][2]), "r"(a[mi][3]),
                          "r"(bh[p][0]), "r"(bh[p][2]));
                    asm volatile(
                        "mma.sync.aligned.m16n8k16.row.col.f32.f16.f16.f32 "
                        "{%0,%1,%2,%3},{%4,%5,%6,%7},{%8,%9},{%0,%1,%2,%3};"
                        : "+f"(acc[mi][2*p+1][0]), "+f"(acc[mi][2*p+1][1]),
                          "+f"(acc[mi][2*p+1][2]), "+f"(acc[mi][2*p+1][3])
                        : "r"(a[mi][0]), "r"(a[mi][1]), "r"(a[mi][2]), "r"(a[mi][3]),
                          "r"(bh[p][1]), "r"(bh[p][3]));
                }
            }
        }
        __syncthreads();
    }

    // epilogue: acc -> g_B
    float* Cn = g_B + (size_t)n * C * C;
    const int mrow0 = tm * 128 + wm * 32 + (lane >> 2);
    const int ncol0 = tn * 128 + wn * 64 + (lane & 3) * 2;
    #pragma unroll
    for (int mi = 0; mi < 2; mi++) {
        #pragma unroll
        for (int ni = 0; ni < 8; ni++) {
            const int r = mrow0 + mi * 16;
            const int cc = ncol0 + ni * 8;
            *(float2*)&Cn[(size_t)r * C + cc]       = make_float2(acc[mi][ni][0], acc[mi][ni][1]);
            *(float2*)&Cn[(size_t)(r + 8) * C + cc] = make_float2(acc[mi][ni][2], acc[mi][ni][3]);
        }
    }
}

// ---------------- kernel 3: softmax over d of (invZ_c * B[c,:]), in place ----------------
__global__ void k_bsoftmax() {
    size_t row = blockIdx.x;  // n*C + c
    float4* br = (float4*)(g_B + row * (size_t)C);
    float iz = g_invZ[row];
    int t = threadIdx.x;      // 128 threads, 4 values each
    float4 v4 = br[t];
    float v[4] = {v4.x * iz, v4.y * iz, v4.z * iz, v4.w * iz};
    float m = fmaxf(fmaxf(v[0], v[1]), fmaxf(v[2], v[3]));
    m = blockReduceMax(m);
    float s = 0.0f;
    #pragma unroll
    for (int j = 0; j < 4; j++) { v[j] = __expf(v[j] - m); s += v[j]; }
    s = blockReduceSum(s);
    float inv = 1.0f / s;
    br[t] = make_float4(v[0] * inv, v[1] * inv, v[2] * inv, v[3] * inv);
}

// ---------------- kernel 3b: w[n,d] = sum_c P[n,c,d] ----------------
__global__ void k_colsum() {
    int n = blockIdx.x;
    int dl = threadIdx.x & 127;
    int q  = threadIdx.x >> 7;    // 0..3
    int d  = blockIdx.y * 128 + dl;
    const float* Bn = g_B + (size_t)n * C * C + d;
    float s = 0.0f;
    #pragma unroll 8
    for (int c = q * 128; c < q * 128 + 128; c++) s += Bn[(size_t)c * C];
    __shared__ float sh[4][128];
    sh[q][dl] = s;
    __syncthreads();
    if (q == 0) g_w[n * C + d] = (sh[0][dl] + sh[1][dl]) + (sh[2][dl] + sh[3][dl]);
}

// ---------------- kernel 4: out[n,s] = sum_d w[n,d] * x[n,d,s] ----------------
__global__ void k_out(const float* __restrict__ x, float* __restrict__ out) {
    int n = blockIdx.y;
    int s = blockIdx.x * 256 + threadIdx.x;
    __shared__ float ws[C];
    for (int i = threadIdx.x; i < C; i += 256) ws[i] = g_w[n * C + i];
    __syncthreads();
    if (s >= S) return;
    const float* fb = x + (size_t)n * C * S + s;
    float a0 = 0, a1 = 0, a2 = 0, a3 = 0;
    #pragma unroll 2
    for (int d = 0; d < C; d += 4) {
        a0 = fmaf(ws[d + 0], fb[(size_t)(d + 0) * S], a0);
        a1 = fmaf(ws[d + 1], fb[(size_t)(d + 1) * S], a1);
        a2 = fmaf(ws[d + 2], fb[(size_t)(d + 2) * S], a2);
        a3 = fmaf(ws[d + 3], fb[(size_t)(d + 3) * S], a3);
    }
    out[n * S + s] = (a0 + a1) + (a2 + a3);
}

extern "C" void kernel_launch(void* const* d_in, const int* in_sizes, int n_in,
                              void* d_out, int out_size) {
    const float* x = (const float*)d_in[0];
    float* out = (float*)d_out;

    cudaFuncSetAttribute(k_gemm_mma, cudaFuncAttributeMaxDynamicSharedMemorySize, SMEM_TOTAL);

    k_rowexp<<<NB * C, 256>>>(x);

    dim3 g2(C / 128, C / 128, NB);   // (4,4,32) = 512 CTAs
    k_gemm_mma<<<g2, 256, SMEM_TOTAL>>>(x);

    k_bsoftmax<<<NB * C, 128>>>();

    dim3 g3(NB, C / 128);            // (32,4)
    k_colsum<<<g3, 512>>>();

    dim3 g4((S + 255) / 256, NB);    // (13,32)
    k_out<<<g4, 256>>>(x, out);
}

// round 7
// speedup vs baseline: 3.8313x; 1.1111x over previous
#include <cuda_runtime.h>
#include <cuda_fp16.h>
#include <math.h>
#include <stdint.h>

#define NB 32
#define C  512
#define S  3136   // 56*56
#define S4 (S/4)
#define BK 32
#define NCHUNK (S / BK)   // 98

// ---------------- scratch (device globals; no allocations allowed) ----------------
__device__ __half g_eh[(size_t)NB * C * S];   // fp16(4096 * exp(7*(x - rowmax)))
__device__ __half g_xh[(size_t)NB * C * S];   // fp16(x)
__device__ float g_invZ[NB * C];              // 1 / sum(e')
__device__ float g_B[(size_t)NB * C * C];
__device__ float g_w[NB * C];

__device__ __forceinline__ uint32_t smem_u32(const void* p) {
    uint32_t a;
    asm("{ .reg .u64 t; cvta.to.shared.u64 t, %1; cvt.u32.u64 %0, t; }" : "=r"(a) : "l"(p));
    return a;
}

// ---------------- block reductions ----------------
__device__ __forceinline__ float blockReduceMax(float v) {
    __shared__ float sh[32];
    int lane = threadIdx.x & 31, w = threadIdx.x >> 5;
    __syncthreads();
    #pragma unroll
    for (int o = 16; o; o >>= 1) v = fmaxf(v, __shfl_xor_sync(0xffffffffu, v, o));
    if (lane == 0) sh[w] = v;
    __syncthreads();
    int nw = (blockDim.x + 31) >> 5;
    if (w == 0) {
        v = (lane < nw) ? sh[lane] : -INFINITY;
        #pragma unroll
        for (int o = 16; o; o >>= 1) v = fmaxf(v, __shfl_xor_sync(0xffffffffu, v, o));
        if (lane == 0) sh[0] = v;
    }
    __syncthreads();
    return sh[0];
}
__device__ __forceinline__ float blockReduceSum(float v) {
    __shared__ float sh[32];
    int lane = threadIdx.x & 31, w = threadIdx.x >> 5;
    __syncthreads();
    #pragma unroll
    for (int o = 16; o; o >>= 1) v += __shfl_xor_sync(0xffffffffu, v, o);
    if (lane == 0) sh[w] = v;
    __syncthreads();
    int nw = (blockDim.x + 31) >> 5;
    if (w == 0) {
        v = (lane < nw) ? sh[lane] : 0.0f;
        #pragma unroll
        for (int o = 16; o; o >>= 1) v += __shfl_xor_sync(0xffffffffu, v, o);
        if (lane == 0) sh[0] = v;
    }
    __syncthreads();
    return sh[0];
}

// ---------------- kernel 1: rowmax + scaled exp -> fp16; also x -> fp16 ----------------
__global__ void k_rowexp(const float* __restrict__ x) {
    size_t row = blockIdx.x;  // n*C + c
    const float4* xr = (const float4*)(x + row * S);
    uint2* er = (uint2*)(g_eh + row * S);   // 4 halves per uint2
    uint2* hr = (uint2*)(g_xh + row * S);

    float m = -INFINITY;
    for (int i = threadIdx.x; i < S4; i += blockDim.x) {
        float4 v = xr[i];
        m = fmaxf(m, fmaxf(fmaxf(v.x, v.y), fmaxf(v.z, v.w)));
    }
    m = blockReduceMax(m);

    const float k = 10.098865286222744f;  // 7/ln(2)
    float s = 0.0f;
    for (int i = threadIdx.x; i < S4; i += blockDim.x) {
        float4 v = xr[i];
        __half2 x01 = __halves2half2(__float2half_rn(v.x), __float2half_rn(v.y));
        __half2 x23 = __halves2half2(__float2half_rn(v.z), __float2half_rn(v.w));
        uint2 ho;
        ho.x = *(uint32_t*)&x01;
        ho.y = *(uint32_t*)&x23;
        hr[i] = ho;
        float e0 = exp2f(fmaf(k, v.x - m, 12.0f));   // 4096 * exp(7*(x-m))
        float e1 = exp2f(fmaf(k, v.y - m, 12.0f));
        float e2 = exp2f(fmaf(k, v.z - m, 12.0f));
        float e3 = exp2f(fmaf(k, v.w - m, 12.0f));
        s += (e0 + e1) + (e2 + e3);
        __half2 h01 = __halves2half2(__float2half_rn(e0), __float2half_rn(e1));
        __half2 h23 = __halves2half2(__float2half_rn(e2), __float2half_rn(e3));
        uint2 o;
        o.x = *(uint32_t*)&h01;
        o.y = *(uint32_t*)&h23;
        er[i] = o;
    }
    s = blockReduceSum(s);
    if (threadIdx.x == 0) g_invZ[row] = 1.0f / s;
}

// ---------------- kernel 2: warp-MMA batched GEMM  B[n] = E[n] @ Xh[n]^T ----------------
// 128x128 CTA tile, BK=32, 8 warps (4x2), each warp 32x64; single fp16 term.
// Both operands fp16 in gmem; cp.async 3-stage pipeline, 1 sync per chunk.
#define LDA 40
#define TILE_B (128 * LDA * 2)        // 10240 bytes per tile
#define STAGE_B (2 * TILE_B)          // A, B
#define NSTAGE 3
#define SMEM_TOTAL (NSTAGE * STAGE_B) // 61440

__device__ __forceinline__ void cp16(uint32_t saddr, const void* gptr) {
    asm volatile("cp.async.cg.shared.global [%0], [%1], 16;" :: "r"(saddr), "l"(gptr) : "memory");
}

__global__ __launch_bounds__(256) void k_gemm_mma() {
    extern __shared__ __align__(16) unsigned char sm[];

    const int tid = threadIdx.x, lane = tid & 31, wid = tid >> 5;
    const int n = blockIdx.z, tm = blockIdx.y, tn = blockIdx.x;
    const int wm = wid >> 1, wn = wid & 1;   // warp tile: rows wm*32, cols wn*64

    const size_t nb = (size_t)n * C * S;
    const int lr = tid >> 1;             // 0..127
    const int lc = (tid & 1) * 16;       // 0 or 16 (elems)
    const __half* Aptr = g_eh + nb + (size_t)(tm * 128 + lr) * S + lc;
    const __half* Xptr = g_xh + nb + (size_t)(tn * 128 + lr) * S + lc;
    const uint32_t sRow = (uint32_t)(lr * (LDA * 2) + lc * 2);
    const uint32_t smBase = smem_u32(sm);

    const int q = lane >> 3, r8 = lane & 7;
    const uint32_t laneOff = (uint32_t)((((q & 1) << 3) + r8) * (LDA * 2) + ((q >> 1) << 3) * 2);

    float acc[2][8][4];
    #pragma unroll
    for (int mi = 0; mi < 2; mi++)
        #pragma unroll
        for (int ni = 0; ni < 8; ni++)
            #pragma unroll
            for (int j = 0; j < 4; j++) acc[mi][ni][j] = 0.0f;

    auto issue = [&](int it) {
        const int buf = it % NSTAGE;
        const int k0 = it * BK;
        const uint32_t sa = smBase + (uint32_t)buf * STAGE_B + sRow;
        const __half* ga = Aptr + k0;
        const __half* gx = Xptr + k0;
        cp16(sa, ga);                   cp16(sa + 16, ga + 8);
        cp16(sa + TILE_B, gx);          cp16(sa + TILE_B + 16, gx + 8);
        asm volatile("cp.async.commit_group;" ::: "memory");
    };

    issue(0);
    issue(1);

    for (int it = 0; it < NCHUNK; it++) {
        if (it + 1 < NCHUNK) {
            asm volatile("cp.async.wait_group 1;" ::: "memory");
        } else {
            asm volatile("cp.async.wait_group 0;" ::: "memory");
        }
        __syncthreads();
        if (it + 2 < NCHUNK) issue(it + 2);

        const int buf = it % NSTAGE;
        const uint32_t base = smBase + (uint32_t)buf * STAGE_B;
        const uint32_t aB = base + (uint32_t)(wm * 32) * (LDA * 2) + laneOff;
        const uint32_t bB = base + TILE_B + (uint32_t)(wn * 64) * (LDA * 2) + laneOff;

        #pragma unroll
        for (int kk = 0; kk < 2; kk++) {
            uint32_t a[2][4], bh[4][4];
            #pragma unroll
            for (int mi = 0; mi < 2; mi++) {
                asm volatile("ldmatrix.sync.aligned.m8n8.x4.shared.b16 {%0,%1,%2,%3}, [%4];"
                    : "=r"(a[mi][0]), "=r"(a[mi][1]), "=r"(a[mi][2]), "=r"(a[mi][3])
                    : "r"(aB + (uint32_t)(mi * 16) * (LDA * 2) + (uint32_t)kk * 32));
            }
            #pragma unroll
            for (int p = 0; p < 4; p++) {
                asm volatile("ldmatrix.sync.aligned.m8n8.x4.shared.b16 {%0,%1,%2,%3}, [%4];"
                    : "=r"(bh[p][0]), "=r"(bh[p][1]), "=r"(bh[p][2]), "=r"(bh[p][3])
                    : "r"(bB + (uint32_t)(p * 16) * (LDA * 2) + (uint32_t)kk * 32));
            }
            #pragma unroll
            for (int mi = 0; mi < 2; mi++) {
                #pragma unroll
                for (int p = 0; p < 4; p++) {
                    asm volatile(
                        "mma.sync.aligned.m16n8k16.row.col.f32.f16.f16.f32 "
                        "{%0,%1,%2,%3},{%4,%5,%6,%7},{%8,%9},{%0,%1,%2,%3};"
                        : "+f"(acc[mi][2*p][0]), "+f"(acc[mi][2*p][1]),
                          "+f"(acc[mi][2*p][2]), "+f"(acc[mi][2*p][3])
                        : "r"(a[mi][0]), "r"(a[mi][1]), "r"(a[mi][2]), "r"(a[mi][3]),
                          "r"(bh[p][0]), "r"(bh[p][2]));
                    asm volatile(
                        "mma.sync.aligned.m16n8k16.row.col.f32.f16.f16.f32 "
                        "{%0,%1,%2,%3},{%4,%5,%6,%7},{%8,%9},{%0,%1,%2,%3};"
                        : "+f"(acc[mi][2*p+1][0]), "+f"(acc[mi][2*p+1][1]),
                          "+f"(acc[mi][2*p+1][2]), "+f"(acc[mi][2*p+1][3])
                        : "r"(a[mi][0]), "r"(a[mi][1]), "r"(a[mi][2]), "r"(a[mi][3]),
                          "r"(bh[p][1]), "r"(bh[p][3]));
                }
            }
        }
    }

    // epilogue: acc -> g_B
    float* Cn = g_B + (size_t)n * C * C;
    const int mrow0 = tm * 128 + wm * 32 + (lane >> 2);
    const int ncol0 = tn * 128 + wn * 64 + (lane & 3) * 2;
    #pragma unroll
    for (int mi = 0; mi < 2; mi++) {
        #pragma unroll
        for (int ni = 0; ni < 8; ni++) {
            const int r = mrow0 + mi * 16;
            const int cc = ncol0 + ni * 8;
            *(float2*)&Cn[(size_t)r * C + cc]       = make_float2(acc[mi][ni][0], acc[mi][ni][1]);
            *(float2*)&Cn[(size_t)(r + 8) * C + cc] = make_float2(acc[mi][ni][2], acc[mi][ni][3]);
        }
    }
}

// ---------------- kernel 3: softmax over d of (invZ_c * B[c,:]), in place ----------------
__global__ void k_bsoftmax() {
    size_t row = blockIdx.x;  // n*C + c
    float4* br = (float4*)(g_B + row * (size_t)C);
    float iz = g_invZ[row];
    int t = threadIdx.x;      // 128 threads, 4 values each
    float4 v4 = br[t];
    float v[4] = {v4.x * iz, v4.y * iz, v4.z * iz, v4.w * iz};
    float m = fmaxf(fmaxf(v[0], v[1]), fmaxf(v[2], v[3]));
    m = blockReduceMax(m);
    float s = 0.0f;
    #pragma unroll
    for (int j = 0; j < 4; j++) { v[j] = __expf(v[j] - m); s += v[j]; }
    s = blockReduceSum(s);
    float inv = 1.0f / s;
    br[t] = make_float4(v[0] * inv, v[1] * inv, v[2] * inv, v[3] * inv);
}

// ---------------- kernel 3b: w[n,d] = sum_c P[n,c,d] ----------------
__global__ void k_colsum() {
    int n = blockIdx.x;
    int dl = threadIdx.x & 127;
    int q  = threadIdx.x >> 7;    // 0..3
    int d  = blockIdx.y * 128 + dl;
    const float* Bn = g_B + (size_t)n * C * C + d;
    float s = 0.0f;
    #pragma unroll 8
    for (int c = q * 128; c < q * 128 + 128; c++) s += Bn[(size_t)c * C];
    __shared__ float sh[4][128];
    sh[q][dl] = s;
    __syncthreads();
    if (q == 0) g_w[n * C + d] = (sh[0][dl] + sh[1][dl]) + (sh[2][dl] + sh[3][dl]);
}

// ---------------- kernel 4: out[n,2s..2s+1] = sum_d w[n,d] * xh[n,d,2s..2s+1] ----------------
#define S2 (S / 2)   // 1568 half2 per row
__global__ void k_out(float* __restrict__ out) {
    int n = blockIdx.y;
    int s2 = blockIdx.x * 256 + threadIdx.x;
    __shared__ float ws[C];
    for (int i = threadIdx.x; i < C; i += 256) ws[i] = g_w[n * C + i];
    __syncthreads();
    if (s2 >= S2) return;
    const __half2* fb = (const __half2*)(g_xh + (size_t)n * C * S) + s2;
    float a0 = 0, a1 = 0, b0 = 0, b1 = 0;
    #pragma unroll 4
    for (int d = 0; d < C; d += 2) {
        float2 f0 = __half22float2(fb[(size_t)d * S2]);
        float2 f1 = __half22float2(fb[(size_t)(d + 1) * S2]);
        a0 = fmaf(ws[d], f0.x, a0);
        a1 = fmaf(ws[d], f0.y, a1);
        b0 = fmaf(ws[d + 1], f1.x, b0);
        b1 = fmaf(ws[d + 1], f1.y, b1);
    }
    float2* o = (float2*)(out + (size_t)n * S) + s2;
    *o = make_float2(a0 + b0, a1 + b1);
}

extern "C" void kernel_launch(void* const* d_in, const int* in_sizes, int n_in,
                              void* d_out, int out_size) {
    const float* x = (const float*)d_in[0];
    float* out = (float*)d_out;

    cudaFuncSetAttribute(k_gemm_mma, cudaFuncAttributeMaxDynamicSharedMemorySize, SMEM_TOTAL);

    k_rowexp<<<NB * C, 256>>>(x);

    dim3 g2(C / 128, C / 128, NB);   // (4,4,32) = 512 CTAs
    k_gemm_mma<<<g2, 256, SMEM_TOTAL>>>();

    k_bsoftmax<<<NB * C, 128>>>();

    dim3 g3(NB, C / 128);            // (32,4)
    k_colsum<<<g3, 512>>>();

    dim3 g4((S2 + 255) / 256, NB);   // (7,32)
    k_out<<<g4, 256>>>(out);
}

// round 8
// speedup vs baseline: 3.9482x; 1.0305x over previous
#include <cuda_runtime.h>
#include <cuda_fp16.h>
#include <math.h>
#include <stdint.h>

#define NB 32
#define C  512
#define S  3136   // 56*56
#define S4 (S/4)
#define BK 32
#define NCHUNK (S / BK)   // 98

// ---------------- scratch (device globals; no allocations allowed) ----------------
__device__ __half g_eh[(size_t)NB * C * S];   // fp16(4096 * exp(7*(x - rowmax)))
__device__ __half g_xh[(size_t)NB * C * S];   // fp16(x)
__device__ float g_invZ[NB * C];              // 1 / sum(e')
__device__ float g_B[(size_t)NB * C * C];     // raw bilinear logits (pre-softmax)
__device__ float g_w[NB * C];                 // w[n,d] = sum_c softmax(B)[c,d]

__device__ __forceinline__ uint32_t smem_u32(const void* p) {
    uint32_t a;
    asm("{ .reg .u64 t; cvta.to.shared.u64 t, %1; cvt.u32.u64 %0, t; }" : "=r"(a) : "l"(p));
    return a;
}

// ---------------- block reductions ----------------
__device__ __forceinline__ float blockReduceMax(float v) {
    __shared__ float sh[32];
    int lane = threadIdx.x & 31, w = threadIdx.x >> 5;
    __syncthreads();
    #pragma unroll
    for (int o = 16; o; o >>= 1) v = fmaxf(v, __shfl_xor_sync(0xffffffffu, v, o));
    if (lane == 0) sh[w] = v;
    __syncthreads();
    int nw = (blockDim.x + 31) >> 5;
    if (w == 0) {
        v = (lane < nw) ? sh[lane] : -INFINITY;
        #pragma unroll
        for (int o = 16; o; o >>= 1) v = fmaxf(v, __shfl_xor_sync(0xffffffffu, v, o));
        if (lane == 0) sh[0] = v;
    }
    __syncthreads();
    return sh[0];
}
__device__ __forceinline__ float blockReduceSum(float v) {
    __shared__ float sh[32];
    int lane = threadIdx.x & 31, w = threadIdx.x >> 5;
    __syncthreads();
    #pragma unroll
    for (int o = 16; o; o >>= 1) v += __shfl_xor_sync(0xffffffffu, v, o);
    if (lane == 0) sh[w] = v;
    __syncthreads();
    int nw = (blockDim.x + 31) >> 5;
    if (w == 0) {
        v = (lane < nw) ? sh[lane] : 0.0f;
        #pragma unroll
        for (int o = 16; o; o >>= 1) v += __shfl_xor_sync(0xffffffffu, v, o);
        if (lane == 0) sh[0] = v;
    }
    __syncthreads();
    return sh[0];
}

// ---------------- kernel 1: rowmax + scaled exp -> fp16; x -> fp16. Single global read via SMEM cache.
__global__ void k_rowexp(const float* __restrict__ x) {
    __shared__ __align__(16) float xs[S];   // 12.5 KB row cache
    size_t row = blockIdx.x;  // n*C + c
    const float4* xr = (const float4*)(x + row * S);
    float4* xs4 = (float4*)xs;
    uint2* er = (uint2*)(g_eh + row * S);   // 4 halves per uint2
    uint2* hr = (uint2*)(g_xh + row * S);

    float m = -INFINITY;
    for (int i = threadIdx.x; i < S4; i += blockDim.x) {
        float4 v = xr[i];
        xs4[i] = v;
        m = fmaxf(m, fmaxf(fmaxf(v.x, v.y), fmaxf(v.z, v.w)));
    }
    m = blockReduceMax(m);

    const float k = 10.098865286222744f;  // 7/ln(2)
    float s = 0.0f;
    for (int i = threadIdx.x; i < S4; i += blockDim.x) {
        float4 v = xs4[i];
        __half2 x01 = __halves2half2(__float2half_rn(v.x), __float2half_rn(v.y));
        __half2 x23 = __halves2half2(__float2half_rn(v.z), __float2half_rn(v.w));
        uint2 ho;
        ho.x = *(uint32_t*)&x01;
        ho.y = *(uint32_t*)&x23;
        hr[i] = ho;
        float e0 = exp2f(fmaf(k, v.x - m, 12.0f));   // 4096 * exp(7*(x-m))
        float e1 = exp2f(fmaf(k, v.y - m, 12.0f));
        float e2 = exp2f(fmaf(k, v.z - m, 12.0f));
        float e3 = exp2f(fmaf(k, v.w - m, 12.0f));
        s += (e0 + e1) + (e2 + e3);
        __half2 h01 = __halves2half2(__float2half_rn(e0), __float2half_rn(e1));
        __half2 h23 = __halves2half2(__float2half_rn(e2), __float2half_rn(e3));
        uint2 o;
        o.x = *(uint32_t*)&h01;
        o.y = *(uint32_t*)&h23;
        er[i] = o;
    }
    s = blockReduceSum(s);
    if (threadIdx.x == 0) g_invZ[row] = 1.0f / s;
}

// ---------------- kernel 2: warp-MMA batched GEMM  B[n] = E[n] @ Xh[n]^T ----------------
#define LDA 40
#define TILE_B (128 * LDA * 2)        // 10240 bytes per tile
#define STAGE_B (2 * TILE_B)          // A, B
#define NSTAGE 3
#define SMEM_TOTAL (NSTAGE * STAGE_B) // 61440

__device__ __forceinline__ void cp16(uint32_t saddr, const void* gptr) {
    asm volatile("cp.async.cg.shared.global [%0], [%1], 16;" :: "r"(saddr), "l"(gptr) : "memory");
}

__global__ __launch_bounds__(256) void k_gemm_mma() {
    extern __shared__ __align__(16) unsigned char sm[];

    const int tid = threadIdx.x, lane = tid & 31, wid = tid >> 5;
    const int n = blockIdx.z, tm = blockIdx.y, tn = blockIdx.x;
    const int wm = wid >> 1, wn = wid & 1;   // warp tile: rows wm*32, cols wn*64

    const size_t nb = (size_t)n * C * S;
    const int lr = tid >> 1;             // 0..127
    const int lc = (tid & 1) * 16;       // 0 or 16 (elems)
    const __half* Aptr = g_eh + nb + (size_t)(tm * 128 + lr) * S + lc;
    const __half* Xptr = g_xh + nb + (size_t)(tn * 128 + lr) * S + lc;
    const uint32_t sRow = (uint32_t)(lr * (LDA * 2) + lc * 2);
    const uint32_t smBase = smem_u32(sm);

    const int q = lane >> 3, r8 = lane & 7;
    const uint32_t laneOff = (uint32_t)((((q & 1) << 3) + r8) * (LDA * 2) + ((q >> 1) << 3) * 2);

    float acc[2][8][4];
    #pragma unroll
    for (int mi = 0; mi < 2; mi++)
        #pragma unroll
        for (int ni = 0; ni < 8; ni++)
            #pragma unroll
            for (int j = 0; j < 4; j++) acc[mi][ni][j] = 0.0f;

    auto issue = [&](int it) {
        const int buf = it % NSTAGE;
        const int k0 = it * BK;
        const uint32_t sa = smBase + (uint32_t)buf * STAGE_B + sRow;
        const __half* ga = Aptr + k0;
        const __half* gx = Xptr + k0;
        cp16(sa, ga);                   cp16(sa + 16, ga + 8);
        cp16(sa + TILE_B, gx);          cp16(sa + TILE_B + 16, gx + 8);
        asm volatile("cp.async.commit_group;" ::: "memory");
    };

    issue(0);
    issue(1);

    for (int it = 0; it < NCHUNK; it++) {
        if (it + 1 < NCHUNK) {
            asm volatile("cp.async.wait_group 1;" ::: "memory");
        } else {
            asm volatile("cp.async.wait_group 0;" ::: "memory");
        }
        __syncthreads();
        if (it + 2 < NCHUNK) issue(it + 2);

        const int buf = it % NSTAGE;
        const uint32_t base = smBase + (uint32_t)buf * STAGE_B;
        const uint32_t aB = base + (uint32_t)(wm * 32) * (LDA * 2) + laneOff;
        const uint32_t bB = base + TILE_B + (uint32_t)(wn * 64) * (LDA * 2) + laneOff;

        #pragma unroll
        for (int kk = 0; kk < 2; kk++) {
            uint32_t a[2][4], bh[4][4];
            #pragma unroll
            for (int mi = 0; mi < 2; mi++) {
                asm volatile("ldmatrix.sync.aligned.m8n8.x4.shared.b16 {%0,%1,%2,%3}, [%4];"
                    : "=r"(a[mi][0]), "=r"(a[mi][1]), "=r"(a[mi][2]), "=r"(a[mi][3])
                    : "r"(aB + (uint32_t)(mi * 16) * (LDA * 2) + (uint32_t)kk * 32));
            }
            #pragma unroll
            for (int p = 0; p < 4; p++) {
                asm volatile("ldmatrix.sync.aligned.m8n8.x4.shared.b16 {%0,%1,%2,%3}, [%4];"
                    : "=r"(bh[p][0]), "=r"(bh[p][1]), "=r"(bh[p][2]), "=r"(bh[p][3])
                    : "r"(bB + (uint32_t)(p * 16) * (LDA * 2) + (uint32_t)kk * 32));
            }
            #pragma unroll
            for (int mi = 0; mi < 2; mi++) {
                #pragma unroll
                for (int p = 0; p < 4; p++) {
                    asm volatile(
                        "mma.sync.aligned.m16n8k16.row.col.f32.f16.f16.f32 "
                        "{%0,%1,%2,%3},{%4,%5,%6,%7},{%8,%9},{%0,%1,%2,%3};"
                        : "+f"(acc[mi][2*p][0]), "+f"(acc[mi][2*p][1]),
                          "+f"(acc[mi][2*p][2]), "+f"(acc[mi][2*p][3])
                        : "r"(a[mi][0]), "r"(a[mi][1]), "r"(a[mi][2]), "r"(a[mi][3]),
                          "r"(bh[p][0]), "r"(bh[p][2]));
                    asm volatile(
                        "mma.sync.aligned.m16n8k16.row.col.f32.f16.f16.f32 "
                        "{%0,%1,%2,%3},{%4,%5,%6,%7},{%8,%9},{%0,%1,%2,%3};"
                        : "+f"(acc[mi][2*p+1][0]), "+f"(acc[mi][2*p+1][1]),
                          "+f"(acc[mi][2*p+1][2]), "+f"(acc[mi][2*p+1][3])
                        : "r"(a[mi][0]), "r"(a[mi][1]), "r"(a[mi][2]), "r"(a[mi][3]),
                          "r"(bh[p][1]), "r"(bh[p][3]));
                }
            }
        }
    }

    // epilogue: acc -> g_B
    float* Cn = g_B + (size_t)n * C * C;
    const int mrow0 = tm * 128 + wm * 32 + (lane >> 2);
    const int ncol0 = tn * 128 + wn * 64 + (lane & 3) * 2;
    #pragma unroll
    for (int mi = 0; mi < 2; mi++) {
        #pragma unroll
        for (int ni = 0; ni < 8; ni++) {
            const int r = mrow0 + mi * 16;
            const int cc = ncol0 + ni * 8;
            *(float2*)&Cn[(size_t)r * C + cc]       = make_float2(acc[mi][ni][0], acc[mi][ni][1]);
            *(float2*)&Cn[(size_t)(r + 8) * C + cc] = make_float2(acc[mi][ni][2], acc[mi][ni][3]);
        }
    }
}

// ---------------- kernel z: zero g_w ----------------
__global__ void k_zero() {
    g_w[blockIdx.x * 1024 + threadIdx.x] = 0.0f;
}

// ---------------- kernel 3: fused row-softmax + column-sum ----------------
// grid (NB, 4): CTA = 128 rows of batch n. Warp per row (16 rows/warp).
// Softmax of (invZ_c * B[c,:]) held in registers; per-lane col accumulators;
// cross-warp SMEM reduce; atomicAdd into g_w (4 adds per address).
__global__ void k_bsm() {
    __shared__ float cac[8][C];   // 16 KB
    const int n = blockIdx.x, cb = blockIdx.y;
    const int lane = threadIdx.x & 31, wid = threadIdx.x >> 5;

    float wacc[4][4];
    #pragma unroll
    for (int q = 0; q < 4; q++)
        #pragma unroll
        for (int j = 0; j < 4; j++) wacc[q][j] = 0.0f;

    for (int r = wid; r < 128; r += 8) {
        const int row = cb * 128 + r;
        const float* Br = g_B + (size_t)n * C * C + (size_t)row * C;
        const float iz = g_invZ[n * C + row];
        float4 v[4];
        float m = -INFINITY;
        #pragma unroll
        for (int q = 0; q < 4; q++) {
            v[q] = *(const float4*)(Br + q * 128 + lane * 4);
            v[q].x *= iz; v[q].y *= iz; v[q].z *= iz; v[q].w *= iz;
            m = fmaxf(m, fmaxf(fmaxf(v[q].x, v[q].y), fmaxf(v[q].z, v[q].w)));
        }
        #pragma unroll
        for (int o = 16; o; o >>= 1) m = fmaxf(m, __shfl_xor_sync(0xffffffffu, m, o));
        float s = 0.0f;
        #pragma unroll
        for (int q = 0; q < 4; q++) {
            v[q].x = __expf(v[q].x - m); v[q].y = __expf(v[q].y - m);
            v[q].z = __expf(v[q].z - m); v[q].w = __expf(v[q].w - m);
            s += (v[q].x + v[q].y) + (v[q].z + v[q].w);
        }
        #pragma unroll
        for (int o = 16; o; o >>= 1) s += __shfl_xor_sync(0xffffffffu, s, o);
        const float inv = 1.0f / s;
        #pragma unroll
        for (int q = 0; q < 4; q++) {
            wacc[q][0] = fmaf(v[q].x, inv, wacc[q][0]);
            wacc[q][1] = fmaf(v[q].y, inv, wacc[q][1]);
            wacc[q][2] = fmaf(v[q].z, inv, wacc[q][2]);
            wacc[q][3] = fmaf(v[q].w, inv, wacc[q][3]);
        }
    }
    #pragma unroll
    for (int q = 0; q < 4; q++)
        *(float4*)&cac[wid][q * 128 + lane * 4] =
            make_float4(wacc[q][0], wacc[q][1], wacc[q][2], wacc[q][3]);
    __syncthreads();
    // 256 threads: cols t and t+256
    #pragma unroll
    for (int h = 0; h < 2; h++) {
        const int col = threadIdx.x + h * 256;
        float s = 0.0f;
        #pragma unroll
        for (int w = 0; w < 8; w++) s += cac[w][col];
        atomicAdd(&g_w[n * C + col], s);
    }
}

// ---------------- kernel 4: out[n,2s..2s+1] = sum_d w[n,d] * xh[n,d,2s..2s+1] ----------------
#define S2 (S / 2)   // 1568 half2 per row
__global__ void k_out(float* __restrict__ out) {
    int n = blockIdx.y;
    int s2 = blockIdx.x * 256 + threadIdx.x;
    __shared__ float ws[C];
    for (int i = threadIdx.x; i < C; i += 256) ws[i] = g_w[n * C + i];
    __syncthreads();
    if (s2 >= S2) return;
    const __half2* fb = (const __half2*)(g_xh + (size_t)n * C * S) + s2;
    float a0 = 0, a1 = 0, b0 = 0, b1 = 0;
    #pragma unroll 4
    for (int d = 0; d < C; d += 2) {
        float2 f0 = __half22float2(fb[(size_t)d * S2]);
        float2 f1 = __half22float2(fb[(size_t)(d + 1) * S2]);
        a0 = fmaf(ws[d], f0.x, a0);
        a1 = fmaf(ws[d], f0.y, a1);
        b0 = fmaf(ws[d + 1], f1.x, b0);
        b1 = fmaf(ws[d + 1], f1.y, b1);
    }
    float2* o = (float2*)(out + (size_t)n * S) + s2;
    *o = make_float2(a0 + b0, a1 + b1);
}

extern "C" void kernel_launch(void* const* d_in, const int* in_sizes, int n_in,
                              void* d_out, int out_size) {
    const float* x = (const float*)d_in[0];
    float* out = (float*)d_out;

    cudaFuncSetAttribute(k_gemm_mma, cudaFuncAttributeMaxDynamicSharedMemorySize, SMEM_TOTAL);

    k_rowexp<<<NB * C, 256>>>(x);

    dim3 g2(C / 128, C / 128, NB);   // (4,4,32) = 512 CTAs
    k_gemm_mma<<<g2, 256, SMEM_TOTAL>>>();

    k_zero<<<NB * C / 1024, 1024>>>();   // 16 blocks

    dim3 g3(NB, 4);                  // (32,4)
    k_bsm<<<g3, 256>>>();

    dim3 g4((S2 + 255) / 256, NB);   // (7,32)
    k_out<<<g4, 256>>>(out);
}